// round 3
// baseline (speedup 1.0000x reference)
#include <cuda_runtime.h>
#include <cstdint>

// ---------------------------------------------------------------------------
// GIN regression: 3x (scatter-add agg + MLP(64->64->64) + BN-affine + ReLU),
// then per-graph mean pool + 2-layer head -> [128].
//
// edge_index / batch are INT32 (JAX default x64-disabled materializes int32
// despite the reference's jnp.int64 annotation).
//
// CSR (dst -> srcs) built once per launch with int atomics; each layer is one
// fused kernel: warp-per-node gather-reduce + 2 GEMVs from shared weights.
// No float atomics in the hot path. Device globals referenced directly.
// ---------------------------------------------------------------------------

#define NMAX 100000
#define EMAX 1600000
#define GMAX 128
#define NPB 8   // nodes (warps) per 256-thread block

// scratch (device globals: allocation-free)
__device__ float g_h0[(size_t)NMAX * 64];
__device__ float g_h1[(size_t)NMAX * 64];
__device__ int   g_deg[NMAX];
__device__ int   g_rowptr[NMAX + 1];
__device__ int   g_cursor[NMAX];
__device__ int   g_col[EMAX];
__device__ float g_pooled[GMAX * 64];

// ---------------------------------------------------------------------------
__global__ void zero_deg_kernel(int n) {
    int i = blockIdx.x * blockDim.x + threadIdx.x;
    if (i < n) g_deg[i] = 0;
}

__global__ void hist_kernel(const int* __restrict__ ei, int E) {
    for (int e = blockIdx.x * blockDim.x + threadIdx.x; e < E; e += gridDim.x * blockDim.x) {
        int d = ei[E + e];   // dst row of edge_index[2, E]
        atomicAdd(&g_deg[d], 1);
    }
}

// single-block exclusive scan over deg -> rowptr (+ cursor copy). n <= 100001.
__global__ void scan_kernel(int n) {
    __shared__ int wsum[32];
    __shared__ int carry_s;
    const int tid = threadIdx.x;            // 1024 threads
    const int lane = tid & 31, wid = tid >> 5;
    if (tid == 0) carry_s = 0;
    __syncthreads();
    for (int base = 0; base < n; base += 1024) {
        int i = base + tid;
        int v = (i < n) ? g_deg[i] : 0;
        int x = v;
        #pragma unroll
        for (int o = 1; o < 32; o <<= 1) {
            int y = __shfl_up_sync(0xffffffffu, x, o);
            if (lane >= o) x += y;
        }
        if (lane == 31) wsum[wid] = x;
        __syncthreads();
        if (wid == 0) {
            int w = wsum[lane];
            #pragma unroll
            for (int o = 1; o < 32; o <<= 1) {
                int y = __shfl_up_sync(0xffffffffu, w, o);
                if (lane >= o) w += y;
            }
            wsum[lane] = w;
        }
        __syncthreads();
        int excl = x - v + (wid > 0 ? wsum[wid - 1] : 0) + carry_s;
        if (i < n) { g_rowptr[i] = excl; g_cursor[i] = excl; }
        __syncthreads();                     // everyone done reading carry_s/wsum
        if (tid == 1023) carry_s = excl + v; // inclusive through chunk end
        __syncthreads();
    }
    if (tid == 0) g_rowptr[n] = carry_s;     // == E
}

__global__ void fill_kernel(const int* __restrict__ ei, int E) {
    for (int e = blockIdx.x * blockDim.x + threadIdx.x; e < E; e += gridDim.x * blockDim.x) {
        int s = ei[e];
        int d = ei[E + e];
        int p = atomicAdd(&g_cursor[d], 1);
        g_col[p] = s;
    }
}

// ---------------------------------------------------------------------------
// Fused layer: h_out[n] = relu( gamma*( relu((h[n]+sum_nb h)·W1 + b1)·W2 + b2 ) + beta )
// one warp per node; lane owns channels (2*lane, 2*lane+1).
// in_sel: 0 -> x (param), 1 -> g_h0, 2 -> g_h1 ; out_sel: 1 -> g_h0, 2 -> g_h1.
__global__ __launch_bounds__(256) void layer_kernel(
    const float* __restrict__ x, int in_sel, int out_sel,
    const float* __restrict__ W1, const float* __restrict__ b1,
    const float* __restrict__ W2, const float* __restrict__ b2,
    const float* __restrict__ gamma, const float* __restrict__ beta,
    int n_nodes)
{
    const float* __restrict__ hin  = (in_sel == 0) ? x : (in_sel == 1 ? g_h0 : g_h1);
    float* __restrict__       hout = (out_sel == 1) ? g_h0 : g_h1;

    __shared__ __align__(16) float W1s[64 * 64];
    __shared__ __align__(16) float W2s[64 * 64];
    __shared__ float b1s[64], b2s[64], gs[64], bs[64];
    __shared__ __align__(16) float ts[NPB][64];

    for (int i = threadIdx.x; i < 64 * 64; i += blockDim.x) { W1s[i] = W1[i]; W2s[i] = W2[i]; }
    for (int i = threadIdx.x; i < 64; i += blockDim.x) {
        b1s[i] = b1[i]; b2s[i] = b2[i]; gs[i] = gamma[i]; bs[i] = beta[i];
    }
    __syncthreads();

    const int warp = threadIdx.x >> 5, lane = threadIdx.x & 31;
    const int c0 = 2 * lane, c1 = 2 * lane + 1;

    for (int node = blockIdx.x * NPB + warp; node < n_nodes; node += gridDim.x * NPB) {
        // self term (eps = 0 -> coefficient 1)
        float2 acc = *(const float2*)(hin + (size_t)node * 64 + c0);

        int j = g_rowptr[node];
        const int jend = g_rowptr[node + 1];
        for (; j + 3 < jend; j += 4) {
            int s0 = g_col[j], s1 = g_col[j + 1], s2 = g_col[j + 2], s3 = g_col[j + 3];
            float2 v0 = *(const float2*)(hin + (size_t)s0 * 64 + c0);
            float2 v1 = *(const float2*)(hin + (size_t)s1 * 64 + c0);
            float2 v2 = *(const float2*)(hin + (size_t)s2 * 64 + c0);
            float2 v3 = *(const float2*)(hin + (size_t)s3 * 64 + c0);
            acc.x += (v0.x + v1.x) + (v2.x + v3.x);
            acc.y += (v0.y + v1.y) + (v2.y + v3.y);
        }
        for (; j < jend; j++) {
            int s = g_col[j];
            float2 v = *(const float2*)(hin + (size_t)s * 64 + c0);
            acc.x += v.x; acc.y += v.y;
        }

        ((float2*)ts[warp])[lane] = acc;
        __syncwarp();

        // GEMV 1: u = relu(t @ W1 + b1)
        float u0 = b1s[c0], u1 = b1s[c1];
        #pragma unroll
        for (int k = 0; k < 64; k++) {
            float tk = ts[warp][k];
            float2 w = ((const float2*)(W1s + k * 64))[lane];
            u0 = fmaf(tk, w.x, u0);
            u1 = fmaf(tk, w.y, u1);
        }
        u0 = fmaxf(u0, 0.f); u1 = fmaxf(u1, 0.f);
        __syncwarp();
        ((float2*)ts[warp])[lane] = make_float2(u0, u1);
        __syncwarp();

        // GEMV 2: v = u @ W2 + b2 ; then BN affine + relu
        float v0 = b2s[c0], v1 = b2s[c1];
        #pragma unroll
        for (int k = 0; k < 64; k++) {
            float uk = ts[warp][k];
            float2 w = ((const float2*)(W2s + k * 64))[lane];
            v0 = fmaf(uk, w.x, v0);
            v1 = fmaf(uk, w.y, v1);
        }
        v0 = fmaxf(fmaf(v0, gs[c0], bs[c0]), 0.f);
        v1 = fmaxf(fmaf(v1, gs[c1], bs[c1]), 0.f);
        *(float2*)(hout + (size_t)node * 64 + c0) = make_float2(v0, v1);
        __syncwarp();   // protect ts before next iteration overwrites
    }
}

// ---------------------------------------------------------------------------
// per-graph mean pool; batch is sorted -> binary search segment boundaries
__device__ __forceinline__ int lower_bound_i(const int* a, int n, int key) {
    int lo = 0, hi = n;
    while (lo < hi) {
        int mid = (lo + hi) >> 1;
        if (a[mid] < key) lo = mid + 1; else hi = mid;
    }
    return lo;
}

__global__ void pool_kernel(const int* __restrict__ batch, int n_nodes) {
    const float* __restrict__ h = g_h0;   // final layer output lives in g_h0
    const int g = blockIdx.x;             // 128 blocks, 256 threads
    const int lo = lower_bound_i(batch, n_nodes, g);
    const int hi = lower_bound_i(batch, n_nodes, g + 1);
    const int c = threadIdx.x & 63;
    const int r = threadIdx.x >> 6;       // 4 node-lanes
    float acc = 0.f;
    for (int i = lo + r; i < hi; i += 4) acc += h[(size_t)i * 64 + c];
    __shared__ float sh[256];
    sh[threadIdx.x] = acc;
    __syncthreads();
    if (threadIdx.x < 128) sh[threadIdx.x] += sh[threadIdx.x + 128];
    __syncthreads();
    if (threadIdx.x < 64) {
        float s = sh[threadIdx.x] + sh[threadIdx.x + 64];
        float cnt = (float)(hi - lo);
        g_pooled[g * 64 + threadIdx.x] = s / fmaxf(cnt, 1.f);
    }
}

// head: out[g] = relu(pooled @ fc1 + b) @ fc2 + b ; one thread per graph
__global__ void head_kernel(const float* __restrict__ fc1W, const float* __restrict__ fc1b,
                            const float* __restrict__ fc2W, const float* __restrict__ fc2b,
                            float* __restrict__ out, int G) {
    int g = blockIdx.x * blockDim.x + threadIdx.x;
    if (g >= G) return;
    float p[64];
    #pragma unroll
    for (int k = 0; k < 64; k++) p[k] = g_pooled[g * 64 + k];
    float o = fc2b[0];
    for (int j = 0; j < 32; j++) {
        float a = fc1b[j];
        #pragma unroll
        for (int k = 0; k < 64; k++) a = fmaf(p[k], fc1W[k * 32 + j], a);
        o = fmaf(fmaxf(a, 0.f), fc2W[j], o);
    }
    out[g] = o;
}

// ---------------------------------------------------------------------------
extern "C" void kernel_launch(void* const* d_in, const int* in_sizes, int n_in,
                              void* d_out, int out_size) {
    const float* x     = (const float*)d_in[0];
    const int*   ei    = (const int*)d_in[1];     // int32 edge_index [2, E]
    const int*   batch = (const int*)d_in[2];     // int32, sorted
    const float* W1    = (const float*)d_in[3];
    const float* b1    = (const float*)d_in[4];
    const float* W2    = (const float*)d_in[5];
    const float* b2    = (const float*)d_in[6];
    const float* gamma = (const float*)d_in[7];
    const float* beta  = (const float*)d_in[8];
    const float* fc1W  = (const float*)d_in[9];
    const float* fc1b  = (const float*)d_in[10];
    const float* fc2W  = (const float*)d_in[11];
    const float* fc2b  = (const float*)d_in[12];
    float*       out   = (float*)d_out;

    const int N = in_sizes[0] / 64;
    const int E = in_sizes[1] / 2;
    const int G = out_size;

    // --- CSR build (dst -> src) ---
    zero_deg_kernel<<<(N + 255) / 256, 256>>>(N);
    hist_kernel<<<2048, 256>>>(ei, E);
    scan_kernel<<<1, 1024>>>(N);
    fill_kernel<<<2048, 256>>>(ei, E);

    // --- 3 fused GIN layers, ping-pong h: x -> g_h0 -> g_h1 -> g_h0 ---
    const int LBLOCKS = 1184;  // grid-stride; amortize weight staging
    layer_kernel<<<LBLOCKS, 256>>>(x, 0, 1,
                                   W1 + 0 * 4096, b1 + 0 * 64, W2 + 0 * 4096, b2 + 0 * 64,
                                   gamma + 0 * 64, beta + 0 * 64, N);
    layer_kernel<<<LBLOCKS, 256>>>(x, 1, 2,
                                   W1 + 1 * 4096, b1 + 1 * 64, W2 + 1 * 4096, b2 + 1 * 64,
                                   gamma + 1 * 64, beta + 1 * 64, N);
    layer_kernel<<<LBLOCKS, 256>>>(x, 2, 1,
                                   W1 + 2 * 4096, b1 + 2 * 64, W2 + 2 * 4096, b2 + 2 * 64,
                                   gamma + 2 * 64, beta + 2 * 64, N);

    // --- mean pool + head ---
    pool_kernel<<<G, 256>>>(batch, N);
    head_kernel<<<1, 128>>>(fc1W, fc1b, fc2W, fc2b, out, G);
}

// round 4
// speedup vs baseline: 1.2835x; 1.2835x over previous
#include <cuda_runtime.h>
#include <cstdint>

// ---------------------------------------------------------------------------
// GIN regression: 3x (scatter-add agg + MLP(64->64->64) + BN-affine + ReLU),
// then per-graph mean pool + 2-layer head -> [128].
//
// Layer = per-tile two-phase kernel:
//   phase 1: warp-per-node CSR gather of 64 nodes -> shared transposed tile
//            sh_t[k][node] with XOR swizzle (conflict-limited stores,
//            conflict-FREE float4 GEMM reads)
//   phase 2: register-blocked 64x64x64 GEMM x2 (4 chan x 4 node accum/thread),
//            bias/ReLU/BN in registers, coalesced float4 global stores.
// ---------------------------------------------------------------------------

#define NMAX 100000
#define EMAX 1600000
#define GMAX 128
#define TILE 64          // nodes per block tile

// scratch (device globals: allocation-free)
__device__ float g_h0[(size_t)NMAX * 64];
__device__ float g_h1[(size_t)NMAX * 64];
__device__ int   g_deg[NMAX];
__device__ int   g_rowptr[NMAX + 1];
__device__ int   g_cursor[NMAX];
__device__ int   g_col[EMAX];
__device__ float g_pooled[GMAX * 64];

// ---------------------------------------------------------------------------
__global__ void zero_deg_kernel(int n) {
    int i = blockIdx.x * blockDim.x + threadIdx.x;
    if (i < n) g_deg[i] = 0;
}

__global__ void hist_kernel(const int* __restrict__ ei, int E) {
    for (int e = blockIdx.x * blockDim.x + threadIdx.x; e < E; e += gridDim.x * blockDim.x) {
        int d = ei[E + e];   // dst row of edge_index[2, E]
        atomicAdd(&g_deg[d], 1);
    }
}

// single-block exclusive scan over deg -> rowptr (+ cursor copy). n <= 100001.
__global__ void scan_kernel(int n) {
    __shared__ int wsum[32];
    __shared__ int carry_s;
    const int tid = threadIdx.x;            // 1024 threads
    const int lane = tid & 31, wid = tid >> 5;
    if (tid == 0) carry_s = 0;
    __syncthreads();
    for (int base = 0; base < n; base += 1024) {
        int i = base + tid;
        int v = (i < n) ? g_deg[i] : 0;
        int x = v;
        #pragma unroll
        for (int o = 1; o < 32; o <<= 1) {
            int y = __shfl_up_sync(0xffffffffu, x, o);
            if (lane >= o) x += y;
        }
        if (lane == 31) wsum[wid] = x;
        __syncthreads();
        if (wid == 0) {
            int w = wsum[lane];
            #pragma unroll
            for (int o = 1; o < 32; o <<= 1) {
                int y = __shfl_up_sync(0xffffffffu, w, o);
                if (lane >= o) w += y;
            }
            wsum[lane] = w;
        }
        __syncthreads();
        int excl = x - v + (wid > 0 ? wsum[wid - 1] : 0) + carry_s;
        if (i < n) { g_rowptr[i] = excl; g_cursor[i] = excl; }
        __syncthreads();
        if (tid == 1023) carry_s = excl + v;
        __syncthreads();
    }
    if (tid == 0) g_rowptr[n] = carry_s;     // == E
}

__global__ void fill_kernel(const int* __restrict__ ei, int E) {
    for (int e = blockIdx.x * blockDim.x + threadIdx.x; e < E; e += gridDim.x * blockDim.x) {
        int s = ei[e];
        int d = ei[E + e];
        int p = atomicAdd(&g_cursor[d], 1);
        g_col[p] = s;
    }
}

// ---------------------------------------------------------------------------
// swizzled transposed tile address: logical (channel/k row, node col m)
// column-group (m/4) XOR'd with (row & 15) -> float4 rows reads conflict-free.
__device__ __forceinline__ int swz(int k, int m) {
    return k * 64 + ((m & 60) ^ ((k & 15) << 2)) + (m & 3);
}

__global__ __launch_bounds__(256) void layer_kernel(
    const float* __restrict__ x, int in_sel, int out_sel,
    const float* __restrict__ W1, const float* __restrict__ b1,
    const float* __restrict__ W2, const float* __restrict__ b2,
    const float* __restrict__ gamma, const float* __restrict__ beta,
    int n_nodes)
{
    const float* __restrict__ hin  = (in_sel == 0) ? x : (in_sel == 1 ? g_h0 : g_h1);
    float* __restrict__       hout = (out_sel == 1) ? g_h0 : g_h1;

    __shared__ __align__(16) float W1s[64 * 64];   // 16 KB
    __shared__ __align__(16) float W2s[64 * 64];   // 16 KB
    __shared__ __align__(16) float sh_t[64 * 64];  // 16 KB (total = 48 KB static)

    for (int i = threadIdx.x; i < 64 * 64; i += 256) { W1s[i] = W1[i]; W2s[i] = W2[i]; }

    const int tid  = threadIdx.x;
    const int warp = tid >> 5, lane = tid & 31;
    const int ng4  = (tid & 15) * 4;   // node group (4 nodes)
    const int cg4  = (tid >> 4) * 4;   // channel group (4 channels)
    const int c0 = 2 * lane, c1 = 2 * lane + 1;

    // per-thread channel constants (registers, not shared)
    float b1r[4], b2r[4], gr[4], br[4];
    #pragma unroll
    for (int i = 0; i < 4; i++) {
        b1r[i] = b1[cg4 + i]; b2r[i] = b2[cg4 + i];
        gr[i]  = gamma[cg4 + i]; br[i] = beta[cg4 + i];
    }
    __syncthreads();

    const int ntiles = (n_nodes + TILE - 1) / TILE;
    for (int tile = blockIdx.x; tile < ntiles; tile += gridDim.x) {
        const int base = tile * TILE;

        // ---- phase 1: gather 64 nodes (warp-per-node, 8 nodes/warp) ----
        #pragma unroll 1
        for (int i = 0; i < 8; i++) {
            const int m = warp * 8 + i;
            const int node = base + m;
            if (node < n_nodes) {
                float2 acc = *(const float2*)(hin + (size_t)node * 64 + c0); // self (eps=0)
                int j = g_rowptr[node];
                const int jend = g_rowptr[node + 1];
                for (; j + 3 < jend; j += 4) {
                    int s0 = g_col[j], s1 = g_col[j + 1], s2 = g_col[j + 2], s3 = g_col[j + 3];
                    float2 v0 = *(const float2*)(hin + (size_t)s0 * 64 + c0);
                    float2 v1 = *(const float2*)(hin + (size_t)s1 * 64 + c0);
                    float2 v2 = *(const float2*)(hin + (size_t)s2 * 64 + c0);
                    float2 v3 = *(const float2*)(hin + (size_t)s3 * 64 + c0);
                    acc.x += (v0.x + v1.x) + (v2.x + v3.x);
                    acc.y += (v0.y + v1.y) + (v2.y + v3.y);
                }
                for (; j < jend; j++) {
                    int s = g_col[j];
                    float2 v = *(const float2*)(hin + (size_t)s * 64 + c0);
                    acc.x += v.x; acc.y += v.y;
                }
                sh_t[swz(c0, m)] = acc.x;      // transposed + swizzled store
                sh_t[swz(c1, m)] = acc.y;
            }
        }
        __syncthreads();

        // ---- phase 2a: U = relu(T^T W1 + b1), register-blocked ----
        float a00=0,a01=0,a02=0,a03=0, a10=0,a11=0,a12=0,a13=0;
        float a20=0,a21=0,a22=0,a23=0, a30=0,a31=0,a32=0,a33=0;
        #pragma unroll 8
        for (int k = 0; k < 64; k++) {
            const float4 a = *(const float4*)(sh_t + k * 64 + (ng4 ^ ((k & 15) << 2)));
            const float4 w = *(const float4*)(W1s + k * 64 + cg4);
            a00 = fmaf(w.x, a.x, a00); a01 = fmaf(w.x, a.y, a01); a02 = fmaf(w.x, a.z, a02); a03 = fmaf(w.x, a.w, a03);
            a10 = fmaf(w.y, a.x, a10); a11 = fmaf(w.y, a.y, a11); a12 = fmaf(w.y, a.z, a12); a13 = fmaf(w.y, a.w, a13);
            a20 = fmaf(w.z, a.x, a20); a21 = fmaf(w.z, a.y, a21); a22 = fmaf(w.z, a.z, a22); a23 = fmaf(w.z, a.w, a23);
            a30 = fmaf(w.w, a.x, a30); a31 = fmaf(w.w, a.y, a31); a32 = fmaf(w.w, a.z, a32); a33 = fmaf(w.w, a.w, a33);
        }
        a00 = fmaxf(a00 + b1r[0], 0.f); a01 = fmaxf(a01 + b1r[0], 0.f); a02 = fmaxf(a02 + b1r[0], 0.f); a03 = fmaxf(a03 + b1r[0], 0.f);
        a10 = fmaxf(a10 + b1r[1], 0.f); a11 = fmaxf(a11 + b1r[1], 0.f); a12 = fmaxf(a12 + b1r[1], 0.f); a13 = fmaxf(a13 + b1r[1], 0.f);
        a20 = fmaxf(a20 + b1r[2], 0.f); a21 = fmaxf(a21 + b1r[2], 0.f); a22 = fmaxf(a22 + b1r[2], 0.f); a23 = fmaxf(a23 + b1r[2], 0.f);
        a30 = fmaxf(a30 + b1r[3], 0.f); a31 = fmaxf(a31 + b1r[3], 0.f); a32 = fmaxf(a32 + b1r[3], 0.f); a33 = fmaxf(a33 + b1r[3], 0.f);

        __syncthreads();   // all GEMM1 reads of sh_t done
        // write U back into sh_t (already [chan][node] in registers)
        {
            int k0 = cg4;
            *(float4*)(sh_t + (k0 + 0) * 64 + (ng4 ^ (((k0 + 0) & 15) << 2))) = make_float4(a00, a01, a02, a03);
            *(float4*)(sh_t + (k0 + 1) * 64 + (ng4 ^ (((k0 + 1) & 15) << 2))) = make_float4(a10, a11, a12, a13);
            *(float4*)(sh_t + (k0 + 2) * 64 + (ng4 ^ (((k0 + 2) & 15) << 2))) = make_float4(a20, a21, a22, a23);
            *(float4*)(sh_t + (k0 + 3) * 64 + (ng4 ^ (((k0 + 3) & 15) << 2))) = make_float4(a30, a31, a32, a33);
        }
        __syncthreads();

        // ---- phase 2b: V = relu(gamma*(U^T W2 + b2) + beta) ----
        float v00=0,v01=0,v02=0,v03=0, v10=0,v11=0,v12=0,v13=0;
        float v20=0,v21=0,v22=0,v23=0, v30=0,v31=0,v32=0,v33=0;
        #pragma unroll 8
        for (int k = 0; k < 64; k++) {
            const float4 a = *(const float4*)(sh_t + k * 64 + (ng4 ^ ((k & 15) << 2)));
            const float4 w = *(const float4*)(W2s + k * 64 + cg4);
            v00 = fmaf(w.x, a.x, v00); v01 = fmaf(w.x, a.y, v01); v02 = fmaf(w.x, a.z, v02); v03 = fmaf(w.x, a.w, v03);
            v10 = fmaf(w.y, a.x, v10); v11 = fmaf(w.y, a.y, v11); v12 = fmaf(w.y, a.z, v12); v13 = fmaf(w.y, a.w, v13);
            v20 = fmaf(w.z, a.x, v20); v21 = fmaf(w.z, a.y, v21); v22 = fmaf(w.z, a.z, v22); v23 = fmaf(w.z, a.w, v23);
            v30 = fmaf(w.w, a.x, v30); v31 = fmaf(w.w, a.y, v31); v32 = fmaf(w.w, a.z, v32); v33 = fmaf(w.w, a.w, v33);
        }
        #define BNR(v, i) fmaxf(fmaf((v) + b2r[i], gr[i], br[i]), 0.f)
        v00 = BNR(v00, 0); v01 = BNR(v01, 0); v02 = BNR(v02, 0); v03 = BNR(v03, 0);
        v10 = BNR(v10, 1); v11 = BNR(v11, 1); v12 = BNR(v12, 1); v13 = BNR(v13, 1);
        v20 = BNR(v20, 2); v21 = BNR(v21, 2); v22 = BNR(v22, 2); v23 = BNR(v23, 2);
        v30 = BNR(v30, 3); v31 = BNR(v31, 3); v32 = BNR(v32, 3); v33 = BNR(v33, 3);
        #undef BNR

        // ---- store: register transpose -> hout[node][cg4..cg4+3] ----
        {
            int n0 = base + ng4;
            if (n0 + 0 < n_nodes) *(float4*)(hout + (size_t)(n0 + 0) * 64 + cg4) = make_float4(v00, v10, v20, v30);
            if (n0 + 1 < n_nodes) *(float4*)(hout + (size_t)(n0 + 1) * 64 + cg4) = make_float4(v01, v11, v21, v31);
            if (n0 + 2 < n_nodes) *(float4*)(hout + (size_t)(n0 + 2) * 64 + cg4) = make_float4(v02, v12, v22, v32);
            if (n0 + 3 < n_nodes) *(float4*)(hout + (size_t)(n0 + 3) * 64 + cg4) = make_float4(v03, v13, v23, v33);
        }
        __syncthreads();   // GEMM2 reads done before next tile's phase 1
    }
}

// ---------------------------------------------------------------------------
__device__ __forceinline__ int lower_bound_i(const int* a, int n, int key) {
    int lo = 0, hi = n;
    while (lo < hi) {
        int mid = (lo + hi) >> 1;
        if (a[mid] < key) lo = mid + 1; else hi = mid;
    }
    return lo;
}

__global__ void pool_kernel(const int* __restrict__ batch, int n_nodes) {
    const float* __restrict__ h = g_h0;   // final layer output lives in g_h0
    const int g = blockIdx.x;             // 128 blocks, 256 threads
    const int lo = lower_bound_i(batch, n_nodes, g);
    const int hi = lower_bound_i(batch, n_nodes, g + 1);
    const int c = threadIdx.x & 63;
    const int r = threadIdx.x >> 6;       // 4 node-lanes
    float acc = 0.f;
    for (int i = lo + r; i < hi; i += 4) acc += h[(size_t)i * 64 + c];
    __shared__ float sh[256];
    sh[threadIdx.x] = acc;
    __syncthreads();
    if (threadIdx.x < 128) sh[threadIdx.x] += sh[threadIdx.x + 128];
    __syncthreads();
    if (threadIdx.x < 64) {
        float s = sh[threadIdx.x] + sh[threadIdx.x + 64];
        float cnt = (float)(hi - lo);
        g_pooled[g * 64 + threadIdx.x] = s / fmaxf(cnt, 1.f);
    }
}

__global__ void head_kernel(const float* __restrict__ fc1W, const float* __restrict__ fc1b,
                            const float* __restrict__ fc2W, const float* __restrict__ fc2b,
                            float* __restrict__ out, int G) {
    int g = blockIdx.x * blockDim.x + threadIdx.x;
    if (g >= G) return;
    float p[64];
    #pragma unroll
    for (int k = 0; k < 64; k++) p[k] = g_pooled[g * 64 + k];
    float o = fc2b[0];
    for (int j = 0; j < 32; j++) {
        float a = fc1b[j];
        #pragma unroll
        for (int k = 0; k < 64; k++) a = fmaf(p[k], fc1W[k * 32 + j], a);
        o = fmaf(fmaxf(a, 0.f), fc2W[j], o);
    }
    out[g] = o;
}

// ---------------------------------------------------------------------------
extern "C" void kernel_launch(void* const* d_in, const int* in_sizes, int n_in,
                              void* d_out, int out_size) {
    const float* x     = (const float*)d_in[0];
    const int*   ei    = (const int*)d_in[1];     // int32 edge_index [2, E]
    const int*   batch = (const int*)d_in[2];     // int32, sorted
    const float* W1    = (const float*)d_in[3];
    const float* b1    = (const float*)d_in[4];
    const float* W2    = (const float*)d_in[5];
    const float* b2    = (const float*)d_in[6];
    const float* gamma = (const float*)d_in[7];
    const float* beta  = (const float*)d_in[8];
    const float* fc1W  = (const float*)d_in[9];
    const float* fc1b  = (const float*)d_in[10];
    const float* fc2W  = (const float*)d_in[11];
    const float* fc2b  = (const float*)d_in[12];
    float*       out   = (float*)d_out;

    const int N = in_sizes[0] / 64;
    const int E = in_sizes[1] / 2;
    const int G = out_size;

    // --- CSR build (dst -> src) ---
    zero_deg_kernel<<<(N + 255) / 256, 256>>>(N);
    hist_kernel<<<2048, 256>>>(ei, E);
    scan_kernel<<<1, 1024>>>(N);
    fill_kernel<<<2048, 256>>>(ei, E);

    // --- 3 fused GIN layers, ping-pong h: x -> g_h0 -> g_h1 -> g_h0 ---
    const int LBLOCKS = 592;   // ~4 blocks/SM resident, grid-stride over tiles
    layer_kernel<<<LBLOCKS, 256>>>(x, 0, 1,
                                   W1 + 0 * 4096, b1 + 0 * 64, W2 + 0 * 4096, b2 + 0 * 64,
                                   gamma + 0 * 64, beta + 0 * 64, N);
    layer_kernel<<<LBLOCKS, 256>>>(x, 1, 2,
                                   W1 + 1 * 4096, b1 + 1 * 64, W2 + 1 * 4096, b2 + 1 * 64,
                                   gamma + 1 * 64, beta + 1 * 64, N);
    layer_kernel<<<LBLOCKS, 256>>>(x, 2, 1,
                                   W1 + 2 * 4096, b1 + 2 * 64, W2 + 2 * 4096, b2 + 2 * 64,
                                   gamma + 2 * 64, beta + 2 * 64, N);

    // --- mean pool + head ---
    pool_kernel<<<G, 256>>>(batch, N);
    head_kernel<<<1, 128>>>(fc1W, fc1b, fc2W, fc2b, out, G);
}